// round 13
// baseline (speedup 1.0000x reference)
#include <cuda_runtime.h>

#define N_TOK 16384
#define E_DIM 64
#define NHEAD 8
#define SEQ   1024
#define NBATCH 16

typedef unsigned long long U64;
typedef unsigned U32;

// scratch: fp16 Q/K/V in attention-native layouts; o in fp16 A-frag layout
__device__ U32 g_q[NBATCH * NHEAD * SEQ * 4];  // [b][h][q][dimpair]  (pre-scaled)
__device__ U32 g_k[NBATCH * NHEAD * SEQ * 4];  // [b][h][key][dimpair]
__device__ U32 g_v[NBATCH * NHEAD * 8 * 512];  // [b][h][dim][keypair]
__device__ U32 g_oh[N_TOK * 32];               // [row][dimpair] fp16

// ---------------- helpers ----------------
__device__ __forceinline__ U32 f2h2(float hi, float lo) {  // lo -> low half
    U32 r;
    asm("cvt.rn.f16x2.f32 %0, %1, %2;" : "=r"(r) : "f"(hi), "f"(lo));
    return r;
}
__device__ __forceinline__ U32 h2ex2(U32 x) {
    U32 r;
    asm("ex2.approx.f16x2 %0, %1;" : "=r"(r) : "r"(x));
    return r;
}
__device__ __forceinline__ U32 prmt(U32 a, U32 b, U32 sel) {
    U32 r;
    asm("prmt.b32 %0, %1, %2, %3;" : "=r"(r) : "r"(a), "r"(b), "r"(sel));
    return r;
}
// QK^T: m16n8k8, f16 inputs + f16 accumulators (C=0).
__device__ __forceinline__ void mma_qk_h(U32& d0, U32& d1, U32 a0, U32 a1, U32 b0) {
    asm("mma.sync.aligned.m16n8k8.row.col.f16.f16.f16.f16 "
        "{%0,%1},{%2,%3},{%4},{%5,%6};"
        : "=r"(d0), "=r"(d1)
        : "r"(a0), "r"(a1), "r"(b0), "r"(0u), "r"(0u));
}
// m16n8k16 f16 inputs, f32 accum (accumulating in place)
__device__ __forceinline__ void mma_16816(float& c0, float& c1, float& c2, float& c3,
                                          U32 a0, U32 a1, U32 a2, U32 a3, U32 b0, U32 b1) {
    asm("mma.sync.aligned.m16n8k16.row.col.f32.f16.f16.f32 "
        "{%0,%1,%2,%3},{%4,%5,%6,%7},{%8,%9},{%0,%1,%2,%3};"
        : "+f"(c0), "+f"(c1), "+f"(c2), "+f"(c3)
        : "r"(a0), "r"(a1), "r"(a2), "r"(a3), "r"(b0), "r"(b1));
}

// ================= Kernel 1: QKV projection via HMMA (unchanged winner) =================
#define QKV_SMEM ((128 * 36 + 96 * 36 + 128 * 35) * 4 + 192 * 4)
__global__ void __launch_bounds__(512) k_qkv(const float* __restrict__ x,
                                             const float* __restrict__ W,
                                             const float* __restrict__ bias) {
    extern __shared__ U32 smq[];
    U32* xh = smq;
    U32* wh = xh + 128 * 36;
    U32* vst = wh + 96 * 36;
    float* bs = (float*)(vst + 128 * 35);

    int tid = threadIdx.x;
    int warp = tid >> 5, lane = tid & 31;
    int rwarp = warp & 7, nthalf = warp >> 3;
    int g = lane >> 2, c = lane & 3;
    int y = blockIdx.y;
    int rowbase = blockIdx.x * 128;
    int bt = rowbase >> 10;
    int qloc = rowbase & 1023;

    const float4* x4 = (const float4*)x;
    for (int idx = tid; idx < 2048; idx += 512) {
        int row = idx >> 4, k4 = idx & 15;
        float4 v = x4[(long)(rowbase + row) * 16 + k4];
        xh[row * 36 + 2 * k4] = f2h2(v.y, v.x);
        xh[row * 36 + 2 * k4 + 1] = f2h2(v.w, v.z);
    }
    const float4* W4 = (const float4*)W;
    for (int idx = tid; idx < 1536; idx += 512) {
        int cc = idx >> 4, k4 = idx & 15;
        float4 v = W4[(y * 96 + cc) * 16 + k4];
        wh[cc * 36 + 2 * k4] = f2h2(v.y, v.x);
        wh[cc * 36 + 2 * k4 + 1] = f2h2(v.w, v.z);
    }
    if (tid < 192) bs[tid] = bias[tid];
    __syncthreads();

    int wr0 = rwarp * 16 + g, wr1 = wr0 + 8;
    U32 a[4][4];
#pragma unroll
    for (int ks = 0; ks < 4; ks++) {
        a[ks][0] = xh[wr0 * 36 + ks * 8 + c];
        a[ks][1] = xh[wr1 * 36 + ks * 8 + c];
        a[ks][2] = xh[wr0 * 36 + ks * 8 + c + 4];
        a[ks][3] = xh[wr1 * 36 + ks * 8 + c + 4];
    }

    const float SCL2 = 0.51010927915195162f;
#pragma unroll 1
    for (int ntl2 = 0; ntl2 < 6; ntl2++) {
        int ntl = nthalf * 6 + ntl2;
        int nt = y * 12 + ntl;
        float c0 = 0.f, c1 = 0.f, c2 = 0.f, c3 = 0.f;
        int ncol = ntl * 8 + g;
#pragma unroll
        for (int ks = 0; ks < 4; ks++) {
            U32 b0 = wh[ncol * 36 + ks * 8 + c];
            U32 b1 = wh[ncol * 36 + ks * 8 + c + 4];
            mma_16816(c0, c1, c2, c3, a[ks][0], a[ks][1], a[ks][2], a[ks][3], b0, b1);
        }
        int col0 = nt * 8 + 2 * c;
        float bv0 = bs[col0], bv1 = bs[col0 + 1];
        c0 += bv0; c1 += bv1; c2 += bv0; c3 += bv1;
        if (nt < 8) {
            long base = ((long)(bt * 8 + nt) * 1024 + qloc);
            g_q[(base + wr0) * 4 + c] = f2h2(c1 * SCL2, c0 * SCL2);
            g_q[(base + wr1) * 4 + c] = f2h2(c3 * SCL2, c2 * SCL2);
        } else if (nt < 16) {
            long base = ((long)(bt * 8 + (nt - 8)) * 1024 + qloc);
            g_k[(base + wr0) * 4 + c] = f2h2(c1, c0);
            g_k[(base + wr1) * 4 + c] = f2h2(c3, c2);
        } else {
            vst[wr0 * 35 + (nt - 16) * 4 + c] = f2h2(c1, c0);
            vst[wr1 * 35 + (nt - 16) * 4 + c] = f2h2(c3, c2);
        }
    }
    if (y == 1) {
        __syncthreads();
        int kpbase = qloc >> 1;
        for (int idx = tid; idx < 4096; idx += 512) {
            int d = idx >> 6, t = idx & 63;
            U32 w0 = vst[(2 * t) * 35 + (d >> 1)];
            U32 w1 = vst[(2 * t + 1) * 35 + (d >> 1)];
            U32 o = (d & 1) ? prmt(w0, w1, 0x7632u) : prmt(w0, w1, 0x5410u);
            g_v[((long)(bt * 8 + (d >> 3)) * 8 + (d & 7)) * 512 + kpbase + t] = o;
        }
    }
}

// ================= Kernel 2: attention — two independent chains per warp =================
// 512 CTAs: (b, h, qtile of 256). 256 threads = 8 warps; warp covers q-tiles
// [warp*16, +16) and [128+warp*16, +16): same K/V SMEM loads feed both chains.
#define ATTN_SMEM (1024 * 16 + 8 * 516 * 4)
__global__ void __launch_bounds__(256) k_attn() {
    extern __shared__ U32 smA[];
    U32* Ku = smA;            // [1024 key][4 words]
    U32* Vu = smA + 4096;     // [8 dim][516 keypair words]

    int tid = threadIdx.x;
    int warp = tid >> 5, lane = tid & 31;
    int g = lane >> 2, c = lane & 3;

    int bid = blockIdx.x;  // 512 = 16b * 8h * 4qt
    int b = bid >> 5;
    int h = (bid >> 2) & 7;
    int qt = bid & 3;

    const uint4* Ksrc = (const uint4*)(g_k + (long)(b * 8 + h) * 4096);
    const uint4* Vsrc = (const uint4*)(g_v + (long)(b * 8 + h) * 4096);
#pragma unroll
    for (int i = tid; i < 1024; i += 256) {
        ((uint4*)Ku)[i] = Ksrc[i];
        uint4 v = Vsrc[i];
        int dim = i >> 7, kp = (i & 127) << 2;
        *(uint4*)(Vu + dim * 516 + kp) = v;
    }

    // chain A rows: qlocA, qlocA+8 ; chain B rows: +128
    int qlocA = qt * 256 + warp * 16 + g;
    int qlocB = qlocA + 128;
    long qb = (long)(b * 8 + h) * 1024;
    U32 aqA0 = g_q[(qb + qlocA) * 4 + c];
    U32 aqA1 = g_q[(qb + qlocA + 8) * 4 + c];
    U32 aqB0 = g_q[(qb + qlocB) * 4 + c];
    U32 aqB1 = g_q[(qb + qlocB + 8) * 4 + c];

    float accA0 = 0.f, accA1 = 0.f, accA2 = 0.f, accA3 = 0.f;
    float accB0 = 0.f, accB1 = 0.f, accB2 = 0.f, accB3 = 0.f;
    float lA0 = 0.f, lA1 = 0.f, lA2 = 0.f, lA3 = 0.f;
    float lB0 = 0.f, lB1 = 0.f, lB2 = 0.f, lB3 = 0.f;
    const U32 ONES = 0x3C003C00u;  // half2(1.0, 1.0)
    __syncthreads();

    const U32* Kg = Ku + g * 4 + c;
    const U32* Vg = Vu + g * 516 + c;
#pragma unroll 1
    for (int jo = 0; jo < 8; jo++) {
#pragma unroll
        for (int ji = 0; ji < 8; ji++) {
            int n = jo * 128 + ji * 16;
            U32 kb0 = Kg[n * 4];
            U32 kb1 = Kg[(n + 8) * 4];
            U32 vb0 = Vg[n >> 1];
            U32 vb1 = Vg[(n >> 1) + 4];
            // chain A
            U32 sA0, sA1, sA2, sA3;
            mma_qk_h(sA0, sA1, aqA0, aqA1, kb0);
            mma_qk_h(sA2, sA3, aqA0, aqA1, kb1);
            U32 pA0 = h2ex2(sA0);
            U32 pA1 = h2ex2(sA1);
            U32 pA2 = h2ex2(sA2);
            U32 pA3 = h2ex2(sA3);
            mma_16816(accA0, accA1, accA2, accA3, pA0, pA1, pA2, pA3, vb0, vb1);
            mma_16816(lA0, lA1, lA2, lA3, pA0, pA1, pA2, pA3, ONES, ONES);
            // chain B (independent)
            U32 sB0, sB1, sB2, sB3;
            mma_qk_h(sB0, sB1, aqB0, aqB1, kb0);
            mma_qk_h(sB2, sB3, aqB0, aqB1, kb1);
            U32 pB0 = h2ex2(sB0);
            U32 pB1 = h2ex2(sB1);
            U32 pB2 = h2ex2(sB2);
            U32 pB3 = h2ex2(sB3);
            mma_16816(accB0, accB1, accB2, accB3, pB0, pB1, pB2, pB3, vb0, vb1);
            mma_16816(lB0, lB1, lB2, lB3, pB0, pB1, pB2, pB3, ONES, ONES);
        }
    }

    float invA0 = __fdividef(1.0f, lA0);  // l(row qlocA)
    float invA1 = __fdividef(1.0f, lA2);  // l(row qlocA+8)
    float invB0 = __fdividef(1.0f, lB0);
    float invB1 = __fdividef(1.0f, lB2);

    int rA0 = b * SEQ + qlocA, rA1 = rA0 + 8;
    int rB0 = b * SEQ + qlocB, rB1 = rB0 + 8;
    g_oh[(long)rA0 * 32 + 4 * h + c] = f2h2(accA1 * invA0, accA0 * invA0);
    g_oh[(long)rA1 * 32 + 4 * h + c] = f2h2(accA3 * invA1, accA2 * invA1);
    g_oh[(long)rB0 * 32 + 4 * h + c] = f2h2(accB1 * invB0, accB0 * invB0);
    g_oh[(long)rB1 * 32 + 4 * h + c] = f2h2(accB3 * invB1, accB2 * invB1);
}

// ================= Kernel 3: all-HMMA fused tail (unchanged winner) =================
#define TAIL_SMEM ((4608 + 8704 + 2304 + 4608 + 4352 + 512) * 4)
__global__ void __launch_bounds__(256) k_tail(
    const float* __restrict__ x, const float* __restrict__ Wout, const float* __restrict__ bout,
    const float* __restrict__ g1, const float* __restrict__ be1, const float* __restrict__ g2,
    const float* __restrict__ be2, const float* __restrict__ Wm1, const float* __restrict__ bm1,
    const float* __restrict__ Wm2, const float* __restrict__ bm2, float* __restrict__ out) {
    extern __shared__ U32 smT[];
    U32* oh = smT;
    float* xs = (float*)(smT + 4608);
    U32* wo = smT + 13312;
    U32* w1 = smT + 15616;
    U32* w2 = smT + 20224;
    float* bb = (float*)(smT + 24576);

    int tid = threadIdx.x;
    int warp = tid >> 5, lane = tid & 31;
    int g = lane >> 2, c = lane & 3;
    int rowbase = blockIdx.x * 128;

    const uint4* oh4 = (const uint4*)g_oh;
    for (int idx = tid; idx < 1024; idx += 256) {
        int row = idx >> 3, k4 = idx & 7;
        *(uint4*)(oh + row * 36 + k4 * 4) = oh4[(long)(rowbase + row) * 8 + k4];
    }
    const float4* x4 = (const float4*)x;
    for (int idx = tid; idx < 2048; idx += 256) {
        int row = idx >> 4, k4 = idx & 15;
        *(float4*)(xs + row * 68 + k4 * 4) = x4[(long)(rowbase + row) * 16 + k4];
    }
    const float4* Wo4 = (const float4*)Wout;
    for (int idx = tid; idx < 1024; idx += 256) {
        int cc = idx >> 4, k4 = idx & 15;
        float4 v = Wo4[idx];
        wo[cc * 36 + 2 * k4] = f2h2(v.y, v.x);
        wo[cc * 36 + 2 * k4 + 1] = f2h2(v.w, v.z);
    }
    const float4* W14 = (const float4*)Wm1;
    for (int idx = tid; idx < 2048; idx += 256) {
        int cc = idx >> 4, k4 = idx & 15;
        float4 v = W14[idx];
        w1[cc * 36 + 2 * k4] = f2h2(v.y, v.x);
        w1[cc * 36 + 2 * k4 + 1] = f2h2(v.w, v.z);
    }
    const float4* W24 = (const float4*)Wm2;
    for (int idx = tid; idx < 2048; idx += 256) {
        int cc = idx >> 5, k4 = idx & 31;
        float4 v = W24[idx];
        w2[cc * 68 + 2 * k4] = f2h2(v.y, v.x);
        w2[cc * 68 + 2 * k4 + 1] = f2h2(v.w, v.z);
    }
    if (tid < 64) bb[tid] = bout[tid];
    if (tid < 128) bb[64 + tid] = bm1[tid];
    if (tid < 64) {
        bb[192 + tid] = bm2[tid];
        bb[256 + tid] = g1[tid];
        bb[320 + tid] = be1[tid];
        bb[384 + tid] = g2[tid];
        bb[448 + tid] = be2[tid];
    }
    __syncthreads();

    int wr0 = warp * 16 + g, wr1 = wr0 + 8;

    float tC[8][4];
#pragma unroll
    for (int nt = 0; nt < 8; nt++)
#pragma unroll
        for (int j = 0; j < 4; j++) tC[nt][j] = 0.f;
#pragma unroll
    for (int ks = 0; ks < 4; ks++) {
        U32 a0 = oh[wr0 * 36 + 8 * ks + c];
        U32 a1 = oh[wr1 * 36 + 8 * ks + c];
        U32 a2 = oh[wr0 * 36 + 8 * ks + 4 + c];
        U32 a3 = oh[wr1 * 36 + 8 * ks + 4 + c];
#pragma unroll
        for (int nt = 0; nt < 8; nt++) {
            U32 b0 = wo[(8 * nt + g) * 36 + 8 * ks + c];
            U32 b1 = wo[(8 * nt + g) * 36 + 8 * ks + 4 + c];
            mma_16816(tC[nt][0], tC[nt][1], tC[nt][2], tC[nt][3], a0, a1, a2, a3, b0, b1);
        }
    }

    float s0 = 0.f, q0 = 0.f, s1 = 0.f, q1 = 0.f;
#pragma unroll
    for (int nt = 0; nt < 8; nt++) {
        int col0 = 8 * nt + 2 * c;
        float2 xv0 = *(float2*)(xs + wr0 * 68 + col0);
        float2 xv1 = *(float2*)(xs + wr1 * 68 + col0);
        float bo0 = bb[col0], bo1 = bb[col0 + 1];
        tC[nt][0] += bo0 + xv0.x;
        tC[nt][1] += bo1 + xv0.y;
        tC[nt][2] += bo0 + xv1.x;
        tC[nt][3] += bo1 + xv1.y;
        s0 += tC[nt][0] + tC[nt][1];
        q0 += tC[nt][0] * tC[nt][0] + tC[nt][1] * tC[nt][1];
        s1 += tC[nt][2] + tC[nt][3];
        q1 += tC[nt][2] * tC[nt][2] + tC[nt][3] * tC[nt][3];
    }
    s0 += __shfl_xor_sync(0xffffffffu, s0, 1);
    s0 += __shfl_xor_sync(0xffffffffu, s0, 2);
    q0 += __shfl_xor_sync(0xffffffffu, q0, 1);
    q0 += __shfl_xor_sync(0xffffffffu, q0, 2);
    s1 += __shfl_xor_sync(0xffffffffu, s1, 1);
    s1 += __shfl_xor_sync(0xffffffffu, s1, 2);
    q1 += __shfl_xor_sync(0xffffffffu, q1, 1);
    q1 += __shfl_xor_sync(0xffffffffu, q1, 2);
    float m0 = s0 * (1.f / 64.f), m1 = s1 * (1.f / 64.f);
    float rs0 = rsqrtf(q0 * (1.f / 64.f) - m0 * m0 + 1e-5f);
    float rs1 = rsqrtf(q1 * (1.f / 64.f) - m1 * m1 + 1e-5f);

    float mi[8][4];
#pragma unroll
    for (int nt = 0; nt < 8; nt++) {
        int col0 = 8 * nt + 2 * c;
        float ga0 = bb[256 + col0], ga1 = bb[257 + col0];
        float be0 = bb[320 + col0], be1v = bb[321 + col0];
        mi[nt][0] = (tC[nt][0] - m0) * rs0 * ga0 + be0;
        mi[nt][1] = (tC[nt][1] - m0) * rs0 * ga1 + be1v;
        mi[nt][2] = (tC[nt][2] - m1) * rs1 * ga0 + be0;
        mi[nt][3] = (tC[nt][3] - m1) * rs1 * ga1 + be1v;
    }
    U32 aM[4][4];
#pragma unroll
    for (int ks = 0; ks < 4; ks++) {
        aM[ks][0] = f2h2(mi[2 * ks][1], mi[2 * ks][0]);
        aM[ks][1] = f2h2(mi[2 * ks][3], mi[2 * ks][2]);
        aM[ks][2] = f2h2(mi[2 * ks + 1][1], mi[2 * ks + 1][0]);
        aM[ks][3] = f2h2(mi[2 * ks + 1][3], mi[2 * ks + 1][2]);
    }

    float uC[8][4];
#pragma unroll
    for (int nt = 0; nt < 8; nt++)
#pragma unroll
        for (int j = 0; j < 4; j++) uC[nt][j] = 0.f;

#pragma unroll
    for (int H = 0; H < 2; H++) {
        float hC[8][4];
#pragma unroll
        for (int nt = 0; nt < 8; nt++)
#pragma unroll
            for (int j = 0; j < 4; j++) hC[nt][j] = 0.f;
#pragma unroll
        for (int ks = 0; ks < 4; ks++) {
#pragma unroll
            for (int nt = 0; nt < 8; nt++) {
                U32 b0 = w1[(64 * H + 8 * nt + g) * 36 + 8 * ks + c];
                U32 b1 = w1[(64 * H + 8 * nt + g) * 36 + 8 * ks + 4 + c];
                mma_16816(hC[nt][0], hC[nt][1], hC[nt][2], hC[nt][3],
                          aM[ks][0], aM[ks][1], aM[ks][2], aM[ks][3], b0, b1);
            }
        }
#pragma unroll
        for (int nt = 0; nt < 8; nt++) {
            int hcol0 = 64 * H + 8 * nt + 2 * c;
            float bh0 = bb[64 + hcol0], bh1 = bb[65 + hcol0];
            hC[nt][0] = fmaxf(hC[nt][0] + bh0, 0.f);
            hC[nt][1] = fmaxf(hC[nt][1] + bh1, 0.f);
            hC[nt][2] = fmaxf(hC[nt][2] + bh0, 0.f);
            hC[nt][3] = fmaxf(hC[nt][3] + bh1, 0.f);
        }
#pragma unroll
        for (int ks2 = 0; ks2 < 4; ks2++) {
            U32 a0 = f2h2(hC[2 * ks2][1], hC[2 * ks2][0]);
            U32 a1 = f2h2(hC[2 * ks2][3], hC[2 * ks2][2]);
            U32 a2 = f2h2(hC[2 * ks2 + 1][1], hC[2 * ks2 + 1][0]);
            U32 a3 = f2h2(hC[2 * ks2 + 1][3], hC[2 * ks2 + 1][2]);
#pragma unroll
            for (int nt3 = 0; nt3 < 8; nt3++) {
                U32 b0 = w2[(8 * nt3 + g) * 68 + 8 * (4 * H + ks2) + c];
                U32 b1 = w2[(8 * nt3 + g) * 68 + 8 * (4 * H + ks2) + 4 + c];
                mma_16816(uC[nt3][0], uC[nt3][1], uC[nt3][2], uC[nt3][3], a0, a1, a2, a3, b0, b1);
            }
        }
    }

    float t0 = 0.f, r0q = 0.f, t1 = 0.f, r1q = 0.f;
#pragma unroll
    for (int nt = 0; nt < 8; nt++) {
        int col0 = 8 * nt + 2 * c;
        float bm0 = bb[192 + col0], bm1v = bb[193 + col0];
        uC[nt][0] += bm0 + mi[nt][0];
        uC[nt][1] += bm1v + mi[nt][1];
        uC[nt][2] += bm0 + mi[nt][2];
        uC[nt][3] += bm1v + mi[nt][3];
        t0 += uC[nt][0] + uC[nt][1];
        r0q += uC[nt][0] * uC[nt][0] + uC[nt][1] * uC[nt][1];
        t1 += uC[nt][2] + uC[nt][3];
        r1q += uC[nt][2] * uC[nt][2] + uC[nt][3] * uC[nt][3];
    }
    t0 += __shfl_xor_sync(0xffffffffu, t0, 1);
    t0 += __shfl_xor_sync(0xffffffffu, t0, 2);
    r0q += __shfl_xor_sync(0xffffffffu, r0q, 1);
    r0q += __shfl_xor_sync(0xffffffffu, r0q, 2);
    t1 += __shfl_xor_sync(0xffffffffu, t1, 1);
    t1 += __shfl_xor_sync(0xffffffffu, t1, 2);
    r1q += __shfl_xor_sync(0xffffffffu, r1q, 1);
    r1q += __shfl_xor_sync(0xffffffffu, r1q, 2);
    float mu0 = t0 * (1.f / 64.f), mu1 = t1 * (1.f / 64.f);
    float rz0 = rsqrtf(r0q * (1.f / 64.f) - mu0 * mu0 + 1e-5f);
    float rz1 = rsqrtf(r1q * (1.f / 64.f) - mu1 * mu1 + 1e-5f);

    long ro0 = (long)(rowbase + wr0) * 64;
    long ro1 = (long)(rowbase + wr1) * 64;
#pragma unroll
    for (int nt = 0; nt < 8; nt++) {
        int col0 = 8 * nt + 2 * c;
        float gb0 = bb[384 + col0], gb1 = bb[385 + col0];
        float bz0 = bb[448 + col0], bz1 = bb[449 + col0];
        *(float2*)(out + ro0 + col0) =
            make_float2((uC[nt][0] - mu0) * rz0 * gb0 + bz0, (uC[nt][1] - mu0) * rz0 * gb1 + bz1);
        *(float2*)(out + ro1 + col0) =
            make_float2((uC[nt][2] - mu1) * rz1 * gb0 + bz0, (uC[nt][3] - mu1) * rz1 * gb1 + bz1);
    }
}

extern "C" void kernel_launch(void* const* d_in, const int* in_sizes, int n_in, void* d_out,
                              int out_size) {
    const float* x = (const float*)d_in[0];
    const float* Wqkv = (const float*)d_in[4];
    const float* bqkv = (const float*)d_in[5];
    const float* Wout = (const float*)d_in[6];
    const float* bout = (const float*)d_in[7];
    const float* g1 = (const float*)d_in[8];
    const float* be1 = (const float*)d_in[9];
    const float* g2 = (const float*)d_in[10];
    const float* be2 = (const float*)d_in[11];
    const float* Wm1 = (const float*)d_in[12];
    const float* bm1 = (const float*)d_in[13];
    const float* Wm2 = (const float*)d_in[14];
    const float* bm2 = (const float*)d_in[15];
    float* out = (float*)d_out;

    cudaFuncSetAttribute(k_qkv, cudaFuncAttributeMaxDynamicSharedMemorySize, QKV_SMEM);
    cudaFuncSetAttribute(k_attn, cudaFuncAttributeMaxDynamicSharedMemorySize, ATTN_SMEM);
    cudaFuncSetAttribute(k_tail, cudaFuncAttributeMaxDynamicSharedMemorySize, TAIL_SMEM);

    k_qkv<<<dim3(128, 2), 512, QKV_SMEM>>>(x, Wqkv, bqkv);
    k_attn<<<512, 256, ATTN_SMEM>>>();
    k_tail<<<128, 256, TAIL_SMEM>>>(x, Wout, bout, g1, be1, g2, be2, Wm1, bm1, Wm2, bm2, out);
}

// round 14
// speedup vs baseline: 1.1929x; 1.1929x over previous
#include <cuda_runtime.h>

#define N_TOK 16384
#define E_DIM 64
#define NHEAD 8
#define SEQ   1024
#define NBATCH 16

typedef unsigned long long U64;
typedef unsigned U32;

// scratch: fp16 Q/K/V in attention-native layouts; o in fp16 A-frag layout
__device__ U32 g_q[NBATCH * NHEAD * SEQ * 4];  // [b][h][q][dimpair]  (pre-scaled)
__device__ U32 g_k[NBATCH * NHEAD * SEQ * 4];  // [b][h][key][dimpair]
__device__ U32 g_v[NBATCH * NHEAD * 8 * 512];  // [b][h][dim][keypair]
__device__ U32 g_oh[N_TOK * 32];               // [row][dimpair] fp16

// ---------------- helpers ----------------
__device__ __forceinline__ U32 f2h2(float hi, float lo) {  // lo -> low half
    U32 r;
    asm("cvt.rn.f16x2.f32 %0, %1, %2;" : "=r"(r) : "f"(hi), "f"(lo));
    return r;
}
__device__ __forceinline__ U32 h2ex2(U32 x) {
    U32 r;
    asm("ex2.approx.f16x2 %0, %1;" : "=r"(r) : "r"(x));
    return r;
}
__device__ __forceinline__ U32 hadd2(U32 a, U32 b) {
    U32 r;
    asm("add.rn.f16x2 %0, %1, %2;" : "=r"(r) : "r"(a), "r"(b));
    return r;
}
__device__ __forceinline__ U32 hsub2(U32 a, U32 b) {
    U32 r;
    asm("sub.rn.f16x2 %0, %1, %2;" : "=r"(r) : "r"(a), "r"(b));
    return r;
}
__device__ __forceinline__ U32 hfma2(U32 a, U32 b, U32 c) {
    U32 r;
    asm("fma.rn.f16x2 %0, %1, %2, %3;" : "=r"(r) : "r"(a), "r"(b), "r"(c));
    return r;
}
// fast exp2 on f16x2 via magic-round + deg-3 poly + exponent splice (no MUFU)
__device__ __forceinline__ U32 h2exp_poly(U32 s2) {
    const U32 MAG = 0x66006600u;  // half2(1536, 1536)
    const U32 C3 = 0x2B1B2B1Bu;   // 0.0555041
    const U32 C2 = 0x33B033B0u;   // 0.2402265
    const U32 C1 = 0x398C398Cu;   // 0.6931472
    const U32 C0 = 0x3C003C00u;   // 1.0
    U32 y = hadd2(s2, MAG);       // integer part in low mantissa bits
    U32 t = hsub2(y, MAG);
    U32 f = hsub2(s2, t);         // exact fraction in [-0.5, 0.5]
    U32 p = hfma2(hfma2(hfma2(C3, f, C2), f, C1), f, C0);
    U32 sh = (y << 10) & 0xFC00FC00u;  // (i << 10) per half, bias cancels mod 2^16
    return p + sh;                // exponent add per half (no cross-half carry)
}
__device__ __forceinline__ U32 prmt(U32 a, U32 b, U32 sel) {
    U32 r;
    asm("prmt.b32 %0, %1, %2, %3;" : "=r"(r) : "r"(a), "r"(b), "r"(sel));
    return r;
}
// QK^T: m16n8k8, f16 inputs + f16 accumulators (C=0).
__device__ __forceinline__ void mma_qk_h(U32& d0, U32& d1, U32 a0, U32 a1, U32 b0) {
    asm("mma.sync.aligned.m16n8k8.row.col.f16.f16.f16.f16 "
        "{%0,%1},{%2,%3},{%4},{%5,%6};"
        : "=r"(d0), "=r"(d1)
        : "r"(a0), "r"(a1), "r"(b0), "r"(0u), "r"(0u));
}
// m16n8k16 f16 inputs, f32 accum (accumulating in place)
__device__ __forceinline__ void mma_16816(float& c0, float& c1, float& c2, float& c3,
                                          U32 a0, U32 a1, U32 a2, U32 a3, U32 b0, U32 b1) {
    asm("mma.sync.aligned.m16n8k16.row.col.f32.f16.f16.f32 "
        "{%0,%1,%2,%3},{%4,%5,%6,%7},{%8,%9},{%0,%1,%2,%3};"
        : "+f"(c0), "+f"(c1), "+f"(c2), "+f"(c3)
        : "r"(a0), "r"(a1), "r"(a2), "r"(a3), "r"(b0), "r"(b1));
}

// ================= Kernel 1: QKV projection via HMMA (unchanged winner) =================
#define QKV_SMEM ((128 * 36 + 96 * 36 + 128 * 35) * 4 + 192 * 4)
__global__ void __launch_bounds__(512) k_qkv(const float* __restrict__ x,
                                             const float* __restrict__ W,
                                             const float* __restrict__ bias) {
    extern __shared__ U32 smq[];
    U32* xh = smq;
    U32* wh = xh + 128 * 36;
    U32* vst = wh + 96 * 36;
    float* bs = (float*)(vst + 128 * 35);

    int tid = threadIdx.x;
    int warp = tid >> 5, lane = tid & 31;
    int rwarp = warp & 7, nthalf = warp >> 3;
    int g = lane >> 2, c = lane & 3;
    int y = blockIdx.y;
    int rowbase = blockIdx.x * 128;
    int bt = rowbase >> 10;
    int qloc = rowbase & 1023;

    const float4* x4 = (const float4*)x;
    for (int idx = tid; idx < 2048; idx += 512) {
        int row = idx >> 4, k4 = idx & 15;
        float4 v = x4[(long)(rowbase + row) * 16 + k4];
        xh[row * 36 + 2 * k4] = f2h2(v.y, v.x);
        xh[row * 36 + 2 * k4 + 1] = f2h2(v.w, v.z);
    }
    const float4* W4 = (const float4*)W;
    for (int idx = tid; idx < 1536; idx += 512) {
        int cc = idx >> 4, k4 = idx & 15;
        float4 v = W4[(y * 96 + cc) * 16 + k4];
        wh[cc * 36 + 2 * k4] = f2h2(v.y, v.x);
        wh[cc * 36 + 2 * k4 + 1] = f2h2(v.w, v.z);
    }
    if (tid < 192) bs[tid] = bias[tid];
    __syncthreads();

    int wr0 = rwarp * 16 + g, wr1 = wr0 + 8;
    U32 a[4][4];
#pragma unroll
    for (int ks = 0; ks < 4; ks++) {
        a[ks][0] = xh[wr0 * 36 + ks * 8 + c];
        a[ks][1] = xh[wr1 * 36 + ks * 8 + c];
        a[ks][2] = xh[wr0 * 36 + ks * 8 + c + 4];
        a[ks][3] = xh[wr1 * 36 + ks * 8 + c + 4];
    }

    const float SCL2 = 0.51010927915195162f;
#pragma unroll 1
    for (int ntl2 = 0; ntl2 < 6; ntl2++) {
        int ntl = nthalf * 6 + ntl2;
        int nt = y * 12 + ntl;
        float c0 = 0.f, c1 = 0.f, c2 = 0.f, c3 = 0.f;
        int ncol = ntl * 8 + g;
#pragma unroll
        for (int ks = 0; ks < 4; ks++) {
            U32 b0 = wh[ncol * 36 + ks * 8 + c];
            U32 b1 = wh[ncol * 36 + ks * 8 + c + 4];
            mma_16816(c0, c1, c2, c3, a[ks][0], a[ks][1], a[ks][2], a[ks][3], b0, b1);
        }
        int col0 = nt * 8 + 2 * c;
        float bv0 = bs[col0], bv1 = bs[col0 + 1];
        c0 += bv0; c1 += bv1; c2 += bv0; c3 += bv1;
        if (nt < 8) {
            long base = ((long)(bt * 8 + nt) * 1024 + qloc);
            g_q[(base + wr0) * 4 + c] = f2h2(c1 * SCL2, c0 * SCL2);
            g_q[(base + wr1) * 4 + c] = f2h2(c3 * SCL2, c2 * SCL2);
        } else if (nt < 16) {
            long base = ((long)(bt * 8 + (nt - 8)) * 1024 + qloc);
            g_k[(base + wr0) * 4 + c] = f2h2(c1, c0);
            g_k[(base + wr1) * 4 + c] = f2h2(c3, c2);
        } else {
            vst[wr0 * 35 + (nt - 16) * 4 + c] = f2h2(c1, c0);
            vst[wr1 * 35 + (nt - 16) * 4 + c] = f2h2(c3, c2);
        }
    }
    if (y == 1) {
        __syncthreads();
        int kpbase = qloc >> 1;
        for (int idx = tid; idx < 4096; idx += 512) {
            int d = idx >> 6, t = idx & 63;
            U32 w0 = vst[(2 * t) * 35 + (d >> 1)];
            U32 w1 = vst[(2 * t + 1) * 35 + (d >> 1)];
            U32 o = (d & 1) ? prmt(w0, w1, 0x7632u) : prmt(w0, w1, 0x5410u);
            g_v[((long)(bt * 8 + (d >> 3)) * 8 + (d & 7)) * 512 + kpbase + t] = o;
        }
    }
}

// ================= Kernel 2: attention — hybrid MUFU / f16-bit-trick exp =================
// R10 structure exactly; keys n..n+7 use ex2.f16x2, keys n+8..n+15 use h2exp_poly.
#define ATTN_SMEM (1024 * 16 + 8 * 516 * 4)
__global__ void __launch_bounds__(256) k_attn() {
    extern __shared__ U32 smA[];
    U32* Ku = smA;            // [1024 key][4 words]
    U32* Vu = smA + 4096;     // [8 dim][516 keypair words]

    int tid = threadIdx.x;
    int warp = tid >> 5, lane = tid & 31;
    int g = lane >> 2, c = lane & 3;

    int bid = blockIdx.x;
    int b = bid >> 6;
    int h = (bid >> 3) & 7;
    int qt = bid & 7;

    const uint4* Ksrc = (const uint4*)(g_k + (long)(b * 8 + h) * 4096);
    const uint4* Vsrc = (const uint4*)(g_v + (long)(b * 8 + h) * 4096);
#pragma unroll
    for (int i = tid; i < 1024; i += 256) {
        ((uint4*)Ku)[i] = Ksrc[i];
        uint4 v = Vsrc[i];
        int dim = i >> 7, kp = (i & 127) << 2;
        *(uint4*)(Vu + dim * 516 + kp) = v;
    }

    int qloc0 = qt * 128 + warp * 16 + g;
    int qloc1 = qloc0 + 8;
    long qb = (long)(b * 8 + h) * 1024;
    U32 aq0 = g_q[(qb + qloc0) * 4 + c];
    U32 aq1 = g_q[(qb + qloc1) * 4 + c];

    float acc0 = 0.f, acc1 = 0.f, acc2 = 0.f, acc3 = 0.f;
    float la0 = 0.f, la1 = 0.f, lb2 = 0.f, lb3 = 0.f;
    const U32 ONES = 0x3C003C00u;  // half2(1.0, 1.0)
    __syncthreads();

    const U32* Kg = Ku + g * 4 + c;
    const U32* Vg = Vu + g * 516 + c;
#pragma unroll 1
    for (int jo = 0; jo < 8; jo++) {
#pragma unroll
        for (int ji = 0; ji < 8; ji++) {
            int n = jo * 128 + ji * 16;
            U32 kb0 = Kg[n * 4];
            U32 kb1 = Kg[(n + 8) * 4];
            U32 s0, s1, s2, s3;
            mma_qk_h(s0, s1, aq0, aq1, kb0);
            mma_qk_h(s2, s3, aq0, aq1, kb1);
            U32 p0 = h2ex2(s0);       // MUFU path (keys n..n+7)
            U32 p1 = h2ex2(s1);
            U32 p2 = h2exp_poly(s2);  // fma/alu path (keys n+8..n+15)
            U32 p3 = h2exp_poly(s3);
            U32 vb0 = Vg[n >> 1];
            U32 vb1 = Vg[(n >> 1) + 4];
            mma_16816(acc0, acc1, acc2, acc3, p0, p1, p2, p3, vb0, vb1);
            mma_16816(la0, la1, lb2, lb3, p0, p1, p2, p3, ONES, ONES);
        }
    }

    float invA = __fdividef(1.0f, la0);  // l(row g), fully reduced by ones-MMA
    float invB = __fdividef(1.0f, lb2);  // l(row g+8)

    int r0 = b * SEQ + qloc0, r1 = b * SEQ + qloc1;
    g_oh[(long)r0 * 32 + 4 * h + c] = f2h2(acc1 * invA, acc0 * invA);
    g_oh[(long)r1 * 32 + 4 * h + c] = f2h2(acc3 * invB, acc2 * invB);
}

// ================= Kernel 3: all-HMMA fused tail (unchanged winner) =================
#define TAIL_SMEM ((4608 + 8704 + 2304 + 4608 + 4352 + 512) * 4)
__global__ void __launch_bounds__(256) k_tail(
    const float* __restrict__ x, const float* __restrict__ Wout, const float* __restrict__ bout,
    const float* __restrict__ g1, const float* __restrict__ be1, const float* __restrict__ g2,
    const float* __restrict__ be2, const float* __restrict__ Wm1, const float* __restrict__ bm1,
    const float* __restrict__ Wm2, const float* __restrict__ bm2, float* __restrict__ out) {
    extern __shared__ U32 smT[];
    U32* oh = smT;
    float* xs = (float*)(smT + 4608);
    U32* wo = smT + 13312;
    U32* w1 = smT + 15616;
    U32* w2 = smT + 20224;
    float* bb = (float*)(smT + 24576);

    int tid = threadIdx.x;
    int warp = tid >> 5, lane = tid & 31;
    int g = lane >> 2, c = lane & 3;
    int rowbase = blockIdx.x * 128;

    const uint4* oh4 = (const uint4*)g_oh;
    for (int idx = tid; idx < 1024; idx += 256) {
        int row = idx >> 3, k4 = idx & 7;
        *(uint4*)(oh + row * 36 + k4 * 4) = oh4[(long)(rowbase + row) * 8 + k4];
    }
    const float4* x4 = (const float4*)x;
    for (int idx = tid; idx < 2048; idx += 256) {
        int row = idx >> 4, k4 = idx & 15;
        *(float4*)(xs + row * 68 + k4 * 4) = x4[(long)(rowbase + row) * 16 + k4];
    }
    const float4* Wo4 = (const float4*)Wout;
    for (int idx = tid; idx < 1024; idx += 256) {
        int cc = idx >> 4, k4 = idx & 15;
        float4 v = Wo4[idx];
        wo[cc * 36 + 2 * k4] = f2h2(v.y, v.x);
        wo[cc * 36 + 2 * k4 + 1] = f2h2(v.w, v.z);
    }
    const float4* W14 = (const float4*)Wm1;
    for (int idx = tid; idx < 2048; idx += 256) {
        int cc = idx >> 4, k4 = idx & 15;
        float4 v = W14[idx];
        w1[cc * 36 + 2 * k4] = f2h2(v.y, v.x);
        w1[cc * 36 + 2 * k4 + 1] = f2h2(v.w, v.z);
    }
    const float4* W24 = (const float4*)Wm2;
    for (int idx = tid; idx < 2048; idx += 256) {
        int cc = idx >> 5, k4 = idx & 31;
        float4 v = W24[idx];
        w2[cc * 68 + 2 * k4] = f2h2(v.y, v.x);
        w2[cc * 68 + 2 * k4 + 1] = f2h2(v.w, v.z);
    }
    if (tid < 64) bb[tid] = bout[tid];
    if (tid < 128) bb[64 + tid] = bm1[tid];
    if (tid < 64) {
        bb[192 + tid] = bm2[tid];
        bb[256 + tid] = g1[tid];
        bb[320 + tid] = be1[tid];
        bb[384 + tid] = g2[tid];
        bb[448 + tid] = be2[tid];
    }
    __syncthreads();

    int wr0 = warp * 16 + g, wr1 = wr0 + 8;

    float tC[8][4];
#pragma unroll
    for (int nt = 0; nt < 8; nt++)
#pragma unroll
        for (int j = 0; j < 4; j++) tC[nt][j] = 0.f;
#pragma unroll
    for (int ks = 0; ks < 4; ks++) {
        U32 a0 = oh[wr0 * 36 + 8 * ks + c];
        U32 a1 = oh[wr1 * 36 + 8 * ks + c];
        U32 a2 = oh[wr0 * 36 + 8 * ks + 4 + c];
        U32 a3 = oh[wr1 * 36 + 8 * ks + 4 + c];
#pragma unroll
        for (int nt = 0; nt < 8; nt++) {
            U32 b0 = wo[(8 * nt + g) * 36 + 8 * ks + c];
            U32 b1 = wo[(8 * nt + g) * 36 + 8 * ks + 4 + c];
            mma_16816(tC[nt][0], tC[nt][1], tC[nt][2], tC[nt][3], a0, a1, a2, a3, b0, b1);
        }
    }

    float s0 = 0.f, q0 = 0.f, s1 = 0.f, q1 = 0.f;
#pragma unroll
    for (int nt = 0; nt < 8; nt++) {
        int col0 = 8 * nt + 2 * c;
        float2 xv0 = *(float2*)(xs + wr0 * 68 + col0);
        float2 xv1 = *(float2*)(xs + wr1 * 68 + col0);
        float bo0 = bb[col0], bo1 = bb[col0 + 1];
        tC[nt][0] += bo0 + xv0.x;
        tC[nt][1] += bo1 + xv0.y;
        tC[nt][2] += bo0 + xv1.x;
        tC[nt][3] += bo1 + xv1.y;
        s0 += tC[nt][0] + tC[nt][1];
        q0 += tC[nt][0] * tC[nt][0] + tC[nt][1] * tC[nt][1];
        s1 += tC[nt][2] + tC[nt][3];
        q1 += tC[nt][2] * tC[nt][2] + tC[nt][3] * tC[nt][3];
    }
    s0 += __shfl_xor_sync(0xffffffffu, s0, 1);
    s0 += __shfl_xor_sync(0xffffffffu, s0, 2);
    q0 += __shfl_xor_sync(0xffffffffu, q0, 1);
    q0 += __shfl_xor_sync(0xffffffffu, q0, 2);
    s1 += __shfl_xor_sync(0xffffffffu, s1, 1);
    s1 += __shfl_xor_sync(0xffffffffu, s1, 2);
    q1 += __shfl_xor_sync(0xffffffffu, q1, 1);
    q1 += __shfl_xor_sync(0xffffffffu, q1, 2);
    float m0 = s0 * (1.f / 64.f), m1 = s1 * (1.f / 64.f);
    float rs0 = rsqrtf(q0 * (1.f / 64.f) - m0 * m0 + 1e-5f);
    float rs1 = rsqrtf(q1 * (1.f / 64.f) - m1 * m1 + 1e-5f);

    float mi[8][4];
#pragma unroll
    for (int nt = 0; nt < 8; nt++) {
        int col0 = 8 * nt + 2 * c;
        float ga0 = bb[256 + col0], ga1 = bb[257 + col0];
        float be0 = bb[320 + col0], be1v = bb[321 + col0];
        mi[nt][0] = (tC[nt][0] - m0) * rs0 * ga0 + be0;
        mi[nt][1] = (tC[nt][1] - m0) * rs0 * ga1 + be1v;
        mi[nt][2] = (tC[nt][2] - m1) * rs1 * ga0 + be0;
        mi[nt][3] = (tC[nt][3] - m1) * rs1 * ga1 + be1v;
    }
    U32 aM[4][4];
#pragma unroll
    for (int ks = 0; ks < 4; ks++) {
        aM[ks][0] = f2h2(mi[2 * ks][1], mi[2 * ks][0]);
        aM[ks][1] = f2h2(mi[2 * ks][3], mi[2 * ks][2]);
        aM[ks][2] = f2h2(mi[2 * ks + 1][1], mi[2 * ks + 1][0]);
        aM[ks][3] = f2h2(mi[2 * ks + 1][3], mi[2 * ks + 1][2]);
    }

    float uC[8][4];
#pragma unroll
    for (int nt = 0; nt < 8; nt++)
#pragma unroll
        for (int j = 0; j < 4; j++) uC[nt][j] = 0.f;

#pragma unroll
    for (int H = 0; H < 2; H++) {
        float hC[8][4];
#pragma unroll
        for (int nt = 0; nt < 8; nt++)
#pragma unroll
            for (int j = 0; j < 4; j++) hC[nt][j] = 0.f;
#pragma unroll
        for (int ks = 0; ks < 4; ks++) {
#pragma unroll
            for (int nt = 0; nt < 8; nt++) {
                U32 b0 = w1[(64 * H + 8 * nt + g) * 36 + 8 * ks + c];
                U32 b1 = w1[(64 * H + 8 * nt + g) * 36 + 8 * ks + 4 + c];
                mma_16816(hC[nt][0], hC[nt][1], hC[nt][2], hC[nt][3],
                          aM[ks][0], aM[ks][1], aM[ks][2], aM[ks][3], b0, b1);
            }
        }
#pragma unroll
        for (int nt = 0; nt < 8; nt++) {
            int hcol0 = 64 * H + 8 * nt + 2 * c;
            float bh0 = bb[64 + hcol0], bh1 = bb[65 + hcol0];
            hC[nt][0] = fmaxf(hC[nt][0] + bh0, 0.f);
            hC[nt][1] = fmaxf(hC[nt][1] + bh1, 0.f);
            hC[nt][2] = fmaxf(hC[nt][2] + bh0, 0.f);
            hC[nt][3] = fmaxf(hC[nt][3] + bh1, 0.f);
        }
#pragma unroll
        for (int ks2 = 0; ks2 < 4; ks2++) {
            U32 a0 = f2h2(hC[2 * ks2][1], hC[2 * ks2][0]);
            U32 a1 = f2h2(hC[2 * ks2][3], hC[2 * ks2][2]);
            U32 a2 = f2h2(hC[2 * ks2 + 1][1], hC[2 * ks2 + 1][0]);
            U32 a3 = f2h2(hC[2 * ks2 + 1][3], hC[2 * ks2 + 1][2]);
#pragma unroll
            for (int nt3 = 0; nt3 < 8; nt3++) {
                U32 b0 = w2[(8 * nt3 + g) * 68 + 8 * (4 * H + ks2) + c];
                U32 b1 = w2[(8 * nt3 + g) * 68 + 8 * (4 * H + ks2) + 4 + c];
                mma_16816(uC[nt3][0], uC[nt3][1], uC[nt3][2], uC[nt3][3], a0, a1, a2, a3, b0, b1);
            }
        }
    }

    float t0 = 0.f, r0q = 0.f, t1 = 0.f, r1q = 0.f;
#pragma unroll
    for (int nt = 0; nt < 8; nt++) {
        int col0 = 8 * nt + 2 * c;
        float bm0 = bb[192 + col0], bm1v = bb[193 + col0];
        uC[nt][0] += bm0 + mi[nt][0];
        uC[nt][1] += bm1v + mi[nt][1];
        uC[nt][2] += bm0 + mi[nt][2];
        uC[nt][3] += bm1v + mi[nt][3];
        t0 += uC[nt][0] + uC[nt][1];
        r0q += uC[nt][0] * uC[nt][0] + uC[nt][1] * uC[nt][1];
        t1 += uC[nt][2] + uC[nt][3];
        r1q += uC[nt][2] * uC[nt][2] + uC[nt][3] * uC[nt][3];
    }
    t0 += __shfl_xor_sync(0xffffffffu, t0, 1);
    t0 += __shfl_xor_sync(0xffffffffu, t0, 2);
    r0q += __shfl_xor_sync(0xffffffffu, r0q, 1);
    r0q += __shfl_xor_sync(0xffffffffu, r0q, 2);
    t1 += __shfl_xor_sync(0xffffffffu, t1, 1);
    t1 += __shfl_xor_sync(0xffffffffu, t1, 2);
    r1q += __shfl_xor_sync(0xffffffffu, r1q, 1);
    r1q += __shfl_xor_sync(0xffffffffu, r1q, 2);
    float mu0 = t0 * (1.f / 64.f), mu1 = t1 * (1.f / 64.f);
    float rz0 = rsqrtf(r0q * (1.f / 64.f) - mu0 * mu0 + 1e-5f);
    float rz1 = rsqrtf(r1q * (1.f / 64.f) - mu1 * mu1 + 1e-5f);

    long ro0 = (long)(rowbase + wr0) * 64;
    long ro1 = (long)(rowbase + wr1) * 64;
#pragma unroll
    for (int nt = 0; nt < 8; nt++) {
        int col0 = 8 * nt + 2 * c;
        float gb0 = bb[384 + col0], gb1 = bb[385 + col0];
        float bz0 = bb[448 + col0], bz1 = bb[449 + col0];
        *(float2*)(out + ro0 + col0) =
            make_float2((uC[nt][0] - mu0) * rz0 * gb0 + bz0, (uC[nt][1] - mu0) * rz0 * gb1 + bz1);
        *(float2*)(out + ro1 + col0) =
            make_float2((uC[nt][2] - mu1) * rz1 * gb0 + bz0, (uC[nt][3] - mu1) * rz1 * gb1 + bz1);
    }
}

extern "C" void kernel_launch(void* const* d_in, const int* in_sizes, int n_in, void* d_out,
                              int out_size) {
    const float* x = (const float*)d_in[0];
    const float* Wqkv = (const float*)d_in[4];
    const float* bqkv = (const float*)d_in[5];
    const float* Wout = (const float*)d_in[6];
    const float* bout = (const float*)d_in[7];
    const float* g1 = (const float*)d_in[8];
    const float* be1 = (const float*)d_in[9];
    const float* g2 = (const float*)d_in[10];
    const float* be2 = (const float*)d_in[11];
    const float* Wm1 = (const float*)d_in[12];
    const float* bm1 = (const float*)d_in[13];
    const float* Wm2 = (const float*)d_in[14];
    const float* bm2 = (const float*)d_in[15];
    float* out = (float*)d_out;

    cudaFuncSetAttribute(k_qkv, cudaFuncAttributeMaxDynamicSharedMemorySize, QKV_SMEM);
    cudaFuncSetAttribute(k_attn, cudaFuncAttributeMaxDynamicSharedMemorySize, ATTN_SMEM);
    cudaFuncSetAttribute(k_tail, cudaFuncAttributeMaxDynamicSharedMemorySize, TAIL_SMEM);

    k_qkv<<<dim3(128, 2), 512, QKV_SMEM>>>(x, Wqkv, bqkv);
    k_attn<<<1024, 256, ATTN_SMEM>>>();
    k_tail<<<128, 256, TAIL_SMEM>>>(x, Wout, bout, g1, be1, g2, be2, Wm1, bm1, Wm2, bm2, out);
}